// round 4
// baseline (speedup 1.0000x reference)
#include <cuda_runtime.h>
#include <cuda_bf16.h>
#include <math.h>

#define B_    32
#define H_    32
#define D_    128
#define HID_  4096
#define TH_   12288      // 3*HID
#define BS_   64
#define NBLK_ 16

__device__ float g_qkv[B_ * TH_];    // [b][j] ; j<4096 q, 4096..8191 k, 8192.. v
__device__ float g_attn[B_ * HID_];  // [b][h*128+d]
__device__ float g_cs[B_][64][2];    // rope cos/sin table

typedef unsigned long long u64;

// ---- packed f32x2 helpers (sm_103a dual-FP32 path) ----
__device__ __forceinline__ u64 pack2(float lo, float hi) {
    u64 r; asm("mov.b64 %0, {%1, %2};" : "=l"(r) : "f"(lo), "f"(hi)); return r;
}
__device__ __forceinline__ u64 fma2(u64 a, u64 b, u64 c) {
    u64 d; asm("fma.rn.f32x2 %0, %1, %2, %3;" : "=l"(d) : "l"(a), "l"(b), "l"(c)); return d;
}
__device__ __forceinline__ float hadd2(u64 a) {
    float lo, hi; asm("mov.b64 {%0, %1}, %2;" : "=f"(lo), "=f"(hi) : "l"(a)); return lo + hi;
}

// ---------------------------------------------------------------------------
// Kernel 1: qkv = hidden @ W_pack (32x4096 @ 4096x12288), f32x2 over k.
// grid 384, block 256 (8 warps): 32 cols/block; warp = (32 j-lanes, 4 batches).
// ---------------------------------------------------------------------------
#define KCHUNK 128
__global__ __launch_bounds__(256) void qkv_kernel(const float* __restrict__ hidden,
                                                  const float* __restrict__ W) {
    __shared__ float sh[32][KCHUNK];     // 16 KB
    const int lane = threadIdx.x & 31;
    const int wid  = threadIdx.x >> 5;
    const int j    = blockIdx.x * 32 + lane;
    const int bg   = wid * 4;

    u64 accA[4], accB[4];
#pragma unroll
    for (int i = 0; i < 4; i++) { accA[i] = 0ull; accB[i] = 0ull; }

    const float* wbase = W + j;
    for (int kc = 0; kc < HID_; kc += KCHUNK) {
        __syncthreads();
        // tile load: 32*128 floats = 1024 float4, 256 threads -> 4 each, all in flight
#pragma unroll
        for (int t = 0; t < 4; t++) {
            int idx = threadIdx.x + t * 256;
            int b   = idx >> 5;              // /(KCHUNK/4)=32
            int kk  = (idx & 31) * 4;
            *(float4*)&sh[b][kk] = *(const float4*)&hidden[b * HID_ + kc + kk];
        }
        __syncthreads();

        const float* wp = wbase + (size_t)kc * TH_;
#pragma unroll 4
        for (int k = 0; k < KCHUNK; k += 4) {
            float w0 = wp[0];
            float w1 = wp[TH_];
            float w2 = wp[2 * TH_];
            float w3 = wp[3 * TH_];
            wp += 4 * (size_t)TH_;
            u64 w01 = pack2(w0, w1);
            u64 w23 = pack2(w2, w3);
#pragma unroll
            for (int bb = 0; bb < 4; bb++) {
                ulonglong2 s2 = *(const ulonglong2*)&sh[bg + bb][k];   // broadcast
                accA[bb] = fma2(s2.x, w01, accA[bb]);
                accB[bb] = fma2(s2.y, w23, accB[bb]);
            }
        }
    }
#pragma unroll
    for (int bb = 0; bb < 4; bb++)
        g_qkv[(bg + bb) * TH_ + j] = hadd2(accA[bb]) + hadd2(accB[bb]);
}

// ---------------------------------------------------------------------------
// Kernel 2a: rope table (the only DP math, 2048 threads total)
// ---------------------------------------------------------------------------
__global__ __launch_bounds__(64) void rope_table(const int* __restrict__ hist) {
    const int b = blockIdx.x;
    const int i = threadIdx.x;     // 0..63
    double invd = exp(-(double)i / 64.0 * 9.210340371976184);  // ln(10000)
    double angd = fmod((double)hist[b] * invd, 6.283185307179586476925286766559);
    g_cs[b][i][0] = cosf((float)angd);
    g_cs[b][i][1] = sinf((float)angd);
}

// Kernel 2b: apply rope to q and k in g_qkv. grid (32, 64): y = part*32+h.
__global__ __launch_bounds__(128) void rope_apply(int dummy) {
    const int b    = blockIdx.x;
    const int part = blockIdx.y >> 5;
    const int h    = blockIdx.y & 31;
    const int d    = threadIdx.x;
    const float c = g_cs[b][d & 63][0];
    const float s = g_cs[b][d & 63][1];

    float* p = &g_qkv[b * TH_ + part * HID_ + h * D_];
    float x  = p[d];
    float xr = (d < 64) ? -p[d + 64] : p[d - 64];
    __syncthreads();
    p[d] = x * c + xr * s;
}

// ---------------------------------------------------------------------------
// Kernel 3: attention, two-phase. grid = B*H blocks, 256 threads.
// ---------------------------------------------------------------------------
__global__ __launch_bounds__(256) void attn_kernel(const float* __restrict__ kcache,
                                                   const float* __restrict__ vcache,
                                                   const int* __restrict__ hist,
                                                   const int* __restrict__ boff) {
    const int b = blockIdx.x >> 5;
    const int h = blockIdx.x & 31;
    const int tid  = threadIdx.x;
    const int lane = tid & 31;
    const int wid  = tid >> 5;

    __shared__ int   s_blk[NBLK_];
    __shared__ float s_sc[1024];
    __shared__ float s_red[8];
    __shared__ float s_half[128];

    if (tid < NBLK_) s_blk[tid] = boff[b * NBLK_ + tid];
    __syncthreads();

    const int pos = hist[b];
    const float scale = 0.08838834764831845f;  // 1/sqrt(128)
    const float4 q4 = *(const float4*)&g_qkv[b * TH_ + h * D_ + lane * 4];

    // ---- phase 1: scores ----
    float mloc = -1e30f;
    int s = wid;
    for (; s + 8 < pos; s += 16) {
        int a0 = ((s_blk[s >> 6] * BS_ + (s & 63)) * H_ + h) * D_;
        int s1 = s + 8;
        int a1 = ((s_blk[s1 >> 6] * BS_ + (s1 & 63)) * H_ + h) * D_;
        float4 k0 = *(const float4*)&kcache[a0 + lane * 4];
        float4 k1 = *(const float4*)&kcache[a1 + lane * 4];
        float d0 = q4.x * k0.x + q4.y * k0.y + q4.z * k0.z + q4.w * k0.w;
        float d1 = q4.x * k1.x + q4.y * k1.y + q4.z * k1.z + q4.w * k1.w;
#pragma unroll
        for (int o = 16; o > 0; o >>= 1) {
            d0 += __shfl_xor_sync(0xffffffffu, d0, o);
            d1 += __shfl_xor_sync(0xffffffffu, d1, o);
        }
        d0 *= scale; d1 *= scale;
        mloc = fmaxf(mloc, fmaxf(d0, d1));
        if (lane == 0) { s_sc[s] = d0; s_sc[s1] = d1; }
    }
    for (; s < pos; s += 8) {
        int a0 = ((s_blk[s >> 6] * BS_ + (s & 63)) * H_ + h) * D_;
        float4 k0 = *(const float4*)&kcache[a0 + lane * 4];
        float d0 = q4.x * k0.x + q4.y * k0.y + q4.z * k0.z + q4.w * k0.w;
#pragma unroll
        for (int o = 16; o > 0; o >>= 1) d0 += __shfl_xor_sync(0xffffffffu, d0, o);
        d0 *= scale;
        mloc = fmaxf(mloc, d0);
        if (lane == 0) s_sc[s] = d0;
    }
    if ((pos & 7) == wid) {      // fresh k at s == pos (ref writes cache first)
        const float* kp = &g_qkv[b * TH_ + HID_ + h * D_];
        float4 k0 = *(const float4*)&kp[lane * 4];
        float d0 = q4.x * k0.x + q4.y * k0.y + q4.z * k0.z + q4.w * k0.w;
#pragma unroll
        for (int o = 16; o > 0; o >>= 1) d0 += __shfl_xor_sync(0xffffffffu, d0, o);
        d0 *= scale;
        mloc = fmaxf(mloc, d0);
        if (lane == 0) s_sc[pos] = d0;
    }

    if (lane == 0) s_red[wid] = mloc;
    __syncthreads();
    float M = -1e30f;
#pragma unroll
    for (int w = 0; w < 8; w++) M = fmaxf(M, s_red[w]);

    float lsum = 0.f;
    for (int i = tid; i <= pos; i += 256) {
        float p = __expf(s_sc[i] - M);
        s_sc[i] = p;
        lsum += p;
    }
#pragma unroll
    for (int o = 16; o > 0; o >>= 1) lsum += __shfl_xor_sync(0xffffffffu, lsum, o);
    __syncthreads();
    if (lane == 0) s_red[wid] = lsum;
    __syncthreads();
    float L = 0.f;
#pragma unroll
    for (int w = 0; w < 8; w++) L += s_red[w];
    const float invL = 1.f / L;

    // ---- phase 2: out[d] = sum_s p[s] * v[s][d], coalesced over d ----
    const int d    = tid & 127;
    const int half = tid >> 7;
    float acc = 0.f;
#pragma unroll 4
    for (int s2 = half; s2 < pos; s2 += 2) {
        int base = ((s_blk[s2 >> 6] * BS_ + (s2 & 63)) * H_ + h) * D_;
        acc += s_sc[s2] * vcache[base + d];
    }
    if ((pos & 1) == half)
        acc += s_sc[pos] * g_qkv[b * TH_ + 2 * HID_ + h * D_ + d];

    if (half == 0) s_half[d] = acc;
    __syncthreads();
    if (half == 1)
        g_attn[b * HID_ + h * D_ + d] = (acc + s_half[d]) * invL;
}

// ---------------------------------------------------------------------------
// Kernel 4: out = attn @ Wo^T, f32x2. block 128 (4 warps), warp = 2 rows x 16 b.
// grid 1024 = 512 row-tiles x 2 batch-halves.
// ---------------------------------------------------------------------------
__global__ __launch_bounds__(128) void oproj_kernel(const float* __restrict__ Wo,
                                                    float* __restrict__ out) {
    __shared__ float s_attn[16][256];    // 16 KB
    const int lane = threadIdx.x & 31;
    const int wid  = threadIdx.x >> 5;
    const int tile = blockIdx.x >> 1;         // 0..511
    const int bh   = (blockIdx.x & 1) * 16;   // batch half
    const int i0   = tile * 8 + wid * 2;

    u64 acc[2][16];
#pragma unroll
    for (int r = 0; r < 2; r++)
#pragma unroll
        for (int b = 0; b < 16; b++) acc[r][b] = 0ull;

    for (int jt = 0; jt < HID_; jt += 256) {
        __syncthreads();
#pragma unroll
        for (int t = 0; t < 8; t++) {
            int idx = threadIdx.x + t * 128;
            int b   = idx >> 6;
            int jj  = (idx & 63) << 2;
            *(float4*)&s_attn[b][jj] = *(const float4*)&g_attn[(bh + b) * HID_ + jt + jj];
        }
        __syncthreads();

        const float* w = Wo + (size_t)i0 * HID_ + jt;
#pragma unroll
        for (int part = 0; part < 2; part++) {
            int j0 = part * 128 + lane * 4;
            ulonglong2 w0 = *(const ulonglong2*)&w[j0];          // 2 f32x2 pairs
            ulonglong2 w1 = *(const ulonglong2*)&w[HID_ + j0];
#pragma unroll
            for (int b = 0; b < 16; b++) {
                ulonglong2 a = *(const ulonglong2*)&s_attn[b][j0];
                acc[0][b] = fma2(a.x, w0.x, acc[0][b]);
                acc[0][b] = fma2(a.y, w0.y, acc[0][b]);
                acc[1][b] = fma2(a.x, w1.x, acc[1][b]);
                acc[1][b] = fma2(a.y, w1.y, acc[1][b]);
            }
        }
    }

#pragma unroll
    for (int r = 0; r < 2; r++) {
        float res = 0.f;
#pragma unroll
        for (int b = 0; b < 16; b++) {
            float v = hadd2(acc[r][b]);
#pragma unroll
            for (int o = 16; o > 0; o >>= 1) v += __shfl_xor_sync(0xffffffffu, v, o);
            if (lane == b) res = v;
        }
        if (lane < 16) out[(bh + lane) * HID_ + i0 + r] = res;
    }
}

// ---------------------------------------------------------------------------
extern "C" void kernel_launch(void* const* d_in, const int* in_sizes, int n_in,
                              void* d_out, int out_size) {
    const float* hidden = (const float*)d_in[0];
    const float* W      = (const float*)d_in[1];
    const float* Wo     = (const float*)d_in[2];
    const float* kcache = (const float*)d_in[3];
    const float* vcache = (const float*)d_in[4];
    const int*   hist   = (const int*)d_in[5];
    const int*   boff   = (const int*)d_in[6];
    float*       out    = (float*)d_out;

    qkv_kernel<<<TH_ / 32, 256>>>(hidden, W);
    rope_table<<<B_, 64>>>(hist);
    rope_apply<<<dim3(B_, 2 * H_), 128>>>(0);
    attn_kernel<<<B_ * H_, 256>>>(kcache, vcache, hist, boff);
    oproj_kernel<<<1024, 128>>>(Wo, out);
}

// round 5
// speedup vs baseline: 1.5432x; 1.5432x over previous
#include <cuda_runtime.h>
#include <cuda_bf16.h>
#include <math.h>

#define B_    32
#define H_    32
#define D_    128
#define HID_  4096
#define TH_   12288      // 3*HID
#define BS_   64
#define NBLK_ 16
#define KSPLIT 4

__device__ float g_part[KSPLIT][B_ * TH_];  // qkv partials (6 MB)
__device__ float g_qkv[B_ * TH_];           // [b][j]; j<4096 q, ..8191 k, .. v
__device__ float g_attn[B_ * HID_];
__device__ float g_cs[B_][64][2];           // rope cos/sin table

typedef unsigned long long u64;

__device__ __forceinline__ u64 pack2(float lo, float hi) {
    u64 r; asm("mov.b64 %0, {%1, %2};" : "=l"(r) : "f"(lo), "f"(hi)); return r;
}
__device__ __forceinline__ u64 fma2(u64 a, u64 b, u64 c) {
    u64 d; asm("fma.rn.f32x2 %0, %1, %2, %3;" : "=l"(d) : "l"(a), "l"(b), "l"(c)); return d;
}
__device__ __forceinline__ float lo2(u64 a) {
    float lo, hi; asm("mov.b64 {%0, %1}, %2;" : "=f"(lo), "=f"(hi) : "l"(a)); return lo;
}
__device__ __forceinline__ float hi2(u64 a) {
    float lo, hi; asm("mov.b64 {%0, %1}, %2;" : "=f"(lo), "=f"(hi) : "l"(a)); return hi;
}
__device__ __forceinline__ float hadd2(u64 a) { return lo2(a) + hi2(a); }

// ---------------------------------------------------------------------------
// Kernel 1: qkv partials. grid (48 j-tiles, KSPLIT), block 256.
// Thread = 4 consecutive j (LDG.128 of W) x 8 batches (4 f32x2 pairs).
// Hidden tile transposed in smem so batch-pairs are natively packed.
// ---------------------------------------------------------------------------
__global__ __launch_bounds__(256) void qkv_part_kernel(const float* __restrict__ hidden,
                                                       const float* __restrict__ W) {
    __shared__ float sh[128][36];        // transposed tile [k][b], pad 36
    const int lane = threadIdx.x & 31;
    const int wid  = threadIdx.x >> 5;
    const int j0   = blockIdx.x * 256 + (wid >> 2) * 128 + lane * 4;
    const int bg   = (wid & 3) * 8;
    const int k0   = blockIdx.y * (HID_ / KSPLIT);   // 1024 k per split

    u64 acc[4][4];   // [j offset][batch pair]
#pragma unroll
    for (int i = 0; i < 4; i++)
#pragma unroll
        for (int p = 0; p < 4; p++) acc[i][p] = 0ull;

    for (int kc = 0; kc < HID_ / KSPLIT; kc += 128) {
        __syncthreads();
        // load+transpose: idx -> (kg = idx>>5, b = lane)
#pragma unroll
        for (int t = 0; t < 4; t++) {
            int idx = threadIdx.x + t * 256;
            int kg  = idx >> 5;
            int b   = idx & 31;
            float4 h4 = *(const float4*)&hidden[b * HID_ + k0 + kc + kg * 4];
            sh[kg * 4 + 0][b] = h4.x;
            sh[kg * 4 + 1][b] = h4.y;
            sh[kg * 4 + 2][b] = h4.z;
            sh[kg * 4 + 3][b] = h4.w;
        }
        __syncthreads();

        const float* wp = W + (size_t)(k0 + kc) * TH_ + j0;
#pragma unroll 2
        for (int k = 0; k < 128; k++) {
            float4 w4 = *(const float4*)wp;          // 4 consecutive j
            wp += TH_;
            ulonglong2 hA = *(const ulonglong2*)&sh[k][bg];      // b pairs 0,1
            ulonglong2 hB = *(const ulonglong2*)&sh[k][bg + 4];  // b pairs 2,3
            u64 wd0 = pack2(w4.x, w4.x);
            u64 wd1 = pack2(w4.y, w4.y);
            u64 wd2 = pack2(w4.z, w4.z);
            u64 wd3 = pack2(w4.w, w4.w);
            acc[0][0] = fma2(hA.x, wd0, acc[0][0]);
            acc[1][0] = fma2(hA.x, wd1, acc[1][0]);
            acc[2][0] = fma2(hA.x, wd2, acc[2][0]);
            acc[3][0] = fma2(hA.x, wd3, acc[3][0]);
            acc[0][1] = fma2(hA.y, wd0, acc[0][1]);
            acc[1][1] = fma2(hA.y, wd1, acc[1][1]);
            acc[2][1] = fma2(hA.y, wd2, acc[2][1]);
            acc[3][1] = fma2(hA.y, wd3, acc[3][1]);
            acc[0][2] = fma2(hB.x, wd0, acc[0][2]);
            acc[1][2] = fma2(hB.x, wd1, acc[1][2]);
            acc[2][2] = fma2(hB.x, wd2, acc[2][2]);
            acc[3][2] = fma2(hB.x, wd3, acc[3][2]);
            acc[0][3] = fma2(hB.y, wd0, acc[0][3]);
            acc[1][3] = fma2(hB.y, wd1, acc[1][3]);
            acc[2][3] = fma2(hB.y, wd2, acc[2][3]);
            acc[3][3] = fma2(hB.y, wd3, acc[3][3]);
        }
    }

    float* outp = &g_part[blockIdx.y][0];
#pragma unroll
    for (int p = 0; p < 4; p++) {
        float4 flo = make_float4(lo2(acc[0][p]), lo2(acc[1][p]), lo2(acc[2][p]), lo2(acc[3][p]));
        float4 fhi = make_float4(hi2(acc[0][p]), hi2(acc[1][p]), hi2(acc[2][p]), hi2(acc[3][p]));
        *(float4*)&outp[(bg + 2 * p) * TH_ + j0]     = flo;
        *(float4*)&outp[(bg + 2 * p + 1) * TH_ + j0] = fhi;
    }
}

// Reduce partials -> g_qkv. grid 384, block 256, float4 per thread.
__global__ __launch_bounds__(256) void qkv_reduce_kernel(int dummy) {
    int i = (blockIdx.x * 256 + threadIdx.x) * 4;
    float4 a = *(const float4*)&g_part[0][i];
    float4 b = *(const float4*)&g_part[1][i];
    float4 c = *(const float4*)&g_part[2][i];
    float4 d = *(const float4*)&g_part[3][i];
    float4 r = make_float4(a.x + b.x + c.x + d.x, a.y + b.y + c.y + d.y,
                           a.z + b.z + c.z + d.z, a.w + b.w + c.w + d.w);
    *(float4*)&g_qkv[i] = r;
}

// ---------------------------------------------------------------------------
// Kernel 2a: rope table (only DP math, 2048 threads)
// ---------------------------------------------------------------------------
__global__ __launch_bounds__(64) void rope_table(const int* __restrict__ hist) {
    const int b = blockIdx.x;
    const int i = threadIdx.x;
    double invd = exp(-(double)i / 64.0 * 9.210340371976184);  // ln(10000)
    double angd = fmod((double)hist[b] * invd, 6.283185307179586476925286766559);
    g_cs[b][i][0] = cosf((float)angd);
    g_cs[b][i][1] = sinf((float)angd);
}

// Kernel 2b: apply rope to q,k. grid (32, 64): y = part*32+h. block 128.
__global__ __launch_bounds__(128) void rope_apply(int dummy) {
    const int b    = blockIdx.x;
    const int part = blockIdx.y >> 5;
    const int h    = blockIdx.y & 31;
    const int d    = threadIdx.x;
    const float c = g_cs[b][d & 63][0];
    const float s = g_cs[b][d & 63][1];

    float* p = &g_qkv[b * TH_ + part * HID_ + h * D_];
    float x  = p[d];
    float xr = (d < 64) ? -p[d + 64] : p[d - 64];
    __syncthreads();
    p[d] = x * c + xr * s;
}

// ---------------------------------------------------------------------------
// Kernel 3: attention, two-phase. grid = B*H blocks, 256 threads.
// ---------------------------------------------------------------------------
__global__ __launch_bounds__(256) void attn_kernel(const float* __restrict__ kcache,
                                                   const float* __restrict__ vcache,
                                                   const int* __restrict__ hist,
                                                   const int* __restrict__ boff) {
    const int b = blockIdx.x >> 5;
    const int h = blockIdx.x & 31;
    const int tid  = threadIdx.x;
    const int lane = tid & 31;
    const int wid  = tid >> 5;

    __shared__ int   s_blk[NBLK_];
    __shared__ float s_sc[1024];
    __shared__ float s_red[8];
    __shared__ float s_half[128];

    if (tid < NBLK_) s_blk[tid] = boff[b * NBLK_ + tid];
    __syncthreads();

    const int pos = hist[b];
    const float scale = 0.08838834764831845f;  // 1/sqrt(128)
    const float4 q4 = *(const float4*)&g_qkv[b * TH_ + h * D_ + lane * 4];

    // ---- phase 1: scores ----
    float mloc = -1e30f;
    int s = wid;
    for (; s + 8 < pos; s += 16) {
        int a0 = ((s_blk[s >> 6] * BS_ + (s & 63)) * H_ + h) * D_;
        int s1 = s + 8;
        int a1 = ((s_blk[s1 >> 6] * BS_ + (s1 & 63)) * H_ + h) * D_;
        float4 k0 = *(const float4*)&kcache[a0 + lane * 4];
        float4 k1 = *(const float4*)&kcache[a1 + lane * 4];
        float d0 = q4.x * k0.x + q4.y * k0.y + q4.z * k0.z + q4.w * k0.w;
        float d1 = q4.x * k1.x + q4.y * k1.y + q4.z * k1.z + q4.w * k1.w;
#pragma unroll
        for (int o = 16; o > 0; o >>= 1) {
            d0 += __shfl_xor_sync(0xffffffffu, d0, o);
            d1 += __shfl_xor_sync(0xffffffffu, d1, o);
        }
        d0 *= scale; d1 *= scale;
        mloc = fmaxf(mloc, fmaxf(d0, d1));
        if (lane == 0) { s_sc[s] = d0; s_sc[s1] = d1; }
    }
    for (; s < pos; s += 8) {
        int a0 = ((s_blk[s >> 6] * BS_ + (s & 63)) * H_ + h) * D_;
        float4 k0 = *(const float4*)&kcache[a0 + lane * 4];
        float d0 = q4.x * k0.x + q4.y * k0.y + q4.z * k0.z + q4.w * k0.w;
#pragma unroll
        for (int o = 16; o > 0; o >>= 1) d0 += __shfl_xor_sync(0xffffffffu, d0, o);
        d0 *= scale;
        mloc = fmaxf(mloc, d0);
        if (lane == 0) s_sc[s] = d0;
    }
    if ((pos & 7) == wid) {      // fresh k at s == pos (ref writes cache first)
        const float* kp = &g_qkv[b * TH_ + HID_ + h * D_];
        float4 k0 = *(const float4*)&kp[lane * 4];
        float d0 = q4.x * k0.x + q4.y * k0.y + q4.z * k0.z + q4.w * k0.w;
#pragma unroll
        for (int o = 16; o > 0; o >>= 1) d0 += __shfl_xor_sync(0xffffffffu, d0, o);
        d0 *= scale;
        mloc = fmaxf(mloc, d0);
        if (lane == 0) s_sc[pos] = d0;
    }

    if (lane == 0) s_red[wid] = mloc;
    __syncthreads();
    float M = -1e30f;
#pragma unroll
    for (int w = 0; w < 8; w++) M = fmaxf(M, s_red[w]);

    float lsum = 0.f;
    for (int i = tid; i <= pos; i += 256) {
        float p = __expf(s_sc[i] - M);
        s_sc[i] = p;
        lsum += p;
    }
#pragma unroll
    for (int o = 16; o > 0; o >>= 1) lsum += __shfl_xor_sync(0xffffffffu, lsum, o);
    __syncthreads();
    if (lane == 0) s_red[wid] = lsum;
    __syncthreads();
    float L = 0.f;
#pragma unroll
    for (int w = 0; w < 8; w++) L += s_red[w];
    const float invL = 1.f / L;

    // ---- phase 2: out[d] = sum_s p[s] * v[s][d], coalesced over d ----
    const int d    = tid & 127;
    const int half = tid >> 7;
    float acc = 0.f;
#pragma unroll 8
    for (int s2 = half; s2 < pos; s2 += 2) {
        int base = ((s_blk[s2 >> 6] * BS_ + (s2 & 63)) * H_ + h) * D_;
        acc += s_sc[s2] * vcache[base + d];
    }
    if ((pos & 1) == half)
        acc += s_sc[pos] * g_qkv[b * TH_ + 2 * HID_ + h * D_ + d];

    if (half == 0) s_half[d] = acc;
    __syncthreads();
    if (half == 1)
        g_attn[b * HID_ + h * D_ + d] = (acc + s_half[d]) * invL;
}

// ---------------------------------------------------------------------------
// Kernel 4: out = attn @ Wo^T, f32x2. block 128, warp = 2 rows x 16 batches.
// grid 1024 = 512 row-tiles x 2 batch-halves.
// ---------------------------------------------------------------------------
__global__ __launch_bounds__(128) void oproj_kernel(const float* __restrict__ Wo,
                                                    float* __restrict__ out) {
    __shared__ float s_attn[16][256];
    const int lane = threadIdx.x & 31;
    const int wid  = threadIdx.x >> 5;
    const int tile = blockIdx.x >> 1;
    const int bh   = (blockIdx.x & 1) * 16;
    const int i0   = tile * 8 + wid * 2;

    u64 acc[2][16];
#pragma unroll
    for (int r = 0; r < 2; r++)
#pragma unroll
        for (int b = 0; b < 16; b++) acc[r][b] = 0ull;

    for (int jt = 0; jt < HID_; jt += 256) {
        __syncthreads();
#pragma unroll
        for (int t = 0; t < 8; t++) {
            int idx = threadIdx.x + t * 128;
            int b   = idx >> 6;
            int jj  = (idx & 63) << 2;
            *(float4*)&s_attn[b][jj] = *(const float4*)&g_attn[(bh + b) * HID_ + jt + jj];
        }
        __syncthreads();

        const float* w = Wo + (size_t)i0 * HID_ + jt;
#pragma unroll
        for (int part = 0; part < 2; part++) {
            int j0 = part * 128 + lane * 4;
            ulonglong2 w0 = *(const ulonglong2*)&w[j0];
            ulonglong2 w1 = *(const ulonglong2*)&w[HID_ + j0];
#pragma unroll
            for (int b = 0; b < 16; b++) {
                ulonglong2 a = *(const ulonglong2*)&s_attn[b][j0];
                acc[0][b] = fma2(a.x, w0.x, acc[0][b]);
                acc[0][b] = fma2(a.y, w0.y, acc[0][b]);
                acc[1][b] = fma2(a.x, w1.x, acc[1][b]);
                acc[1][b] = fma2(a.y, w1.y, acc[1][b]);
            }
        }
    }

#pragma unroll
    for (int r = 0; r < 2; r++) {
        float res = 0.f;
#pragma unroll
        for (int b = 0; b < 16; b++) {
            float v = hadd2(acc[r][b]);
#pragma unroll
            for (int o = 16; o > 0; o >>= 1) v += __shfl_xor_sync(0xffffffffu, v, o);
            if (lane == b) res = v;
        }
        if (lane < 16) out[(bh + lane) * HID_ + i0 + r] = res;
    }
}

// ---------------------------------------------------------------------------
extern "C" void kernel_launch(void* const* d_in, const int* in_sizes, int n_in,
                              void* d_out, int out_size) {
    const float* hidden = (const float*)d_in[0];
    const float* W      = (const float*)d_in[1];
    const float* Wo     = (const float*)d_in[2];
    const float* kcache = (const float*)d_in[3];
    const float* vcache = (const float*)d_in[4];
    const int*   hist   = (const int*)d_in[5];
    const int*   boff   = (const int*)d_in[6];
    float*       out    = (float*)d_out;

    qkv_part_kernel<<<dim3(TH_ / 256, KSPLIT), 256>>>(hidden, W);
    qkv_reduce_kernel<<<B_ * TH_ / 1024, 256>>>(0);
    rope_table<<<B_, 64>>>(hist);
    rope_apply<<<dim3(B_, 2 * H_), 128>>>(0);
    attn_kernel<<<B_ * H_, 256>>>(kcache, vcache, hist, boff);
    oproj_kernel<<<1024, 128>>>(Wo, out);
}

// round 6
// speedup vs baseline: 2.4798x; 1.6070x over previous
#include <cuda_runtime.h>
#include <cuda_bf16.h>
#include <math.h>

#define B_    32
#define H_    32
#define D_    128
#define HID_  4096
#define TH_   12288      // 3*HID
#define BS_   64
#define NBLK_ 16
#define KSPLIT 8

__device__ float g_part[KSPLIT][B_ * TH_];  // qkv partials (12 MB)
__device__ float g_qkv[B_ * TH_];           // [b][j]; j<4096 q, ..8191 k, .. v
__device__ float g_attn[B_ * HID_];
__device__ float g_cs[B_][64][2];           // rope cos/sin table

typedef unsigned long long u64;

__device__ __forceinline__ u64 pack2(float lo, float hi) {
    u64 r; asm("mov.b64 %0, {%1, %2};" : "=l"(r) : "f"(lo), "f"(hi)); return r;
}
__device__ __forceinline__ u64 fma2(u64 a, u64 b, u64 c) {
    u64 d; asm("fma.rn.f32x2 %0, %1, %2, %3;" : "=l"(d) : "l"(a), "l"(b), "l"(c)); return d;
}
__device__ __forceinline__ float lo2(u64 a) {
    float lo, hi; asm("mov.b64 {%0, %1}, %2;" : "=f"(lo), "=f"(hi) : "l"(a)); return lo;
}
__device__ __forceinline__ float hi2(u64 a) {
    float lo, hi; asm("mov.b64 {%0, %1}, %2;" : "=f"(lo), "=f"(hi) : "l"(a)); return hi;
}
__device__ __forceinline__ float hadd2(u64 a) { return lo2(a) + hi2(a); }

// ---------------------------------------------------------------------------
// Kernel 1: qkv partials. grid (48 j-tiles, KSPLIT=8), block 256.
// Thread = 4 consecutive j (W via LDG.128) x 8 batches (4 f32x2 pairs).
// k-loop unroll 8 with register prefetch of 8 W float4s -> MLP 8 per warp.
// ---------------------------------------------------------------------------
__global__ __launch_bounds__(256) void qkv_part_kernel(const float* __restrict__ hidden,
                                                       const float* __restrict__ W) {
    __shared__ float sh[128][36];        // transposed tile [k][b]
    const int lane = threadIdx.x & 31;
    const int wid  = threadIdx.x >> 5;
    const int j0   = blockIdx.x * 256 + (wid >> 2) * 128 + lane * 4;
    const int bg   = (wid & 3) * 8;
    const int k0   = blockIdx.y * (HID_ / KSPLIT);   // 512 k per split

    u64 acc[4][4];
#pragma unroll
    for (int i = 0; i < 4; i++)
#pragma unroll
        for (int p = 0; p < 4; p++) acc[i][p] = 0ull;

    for (int kc = 0; kc < HID_ / KSPLIT; kc += 128) {
        __syncthreads();
#pragma unroll
        for (int t = 0; t < 4; t++) {
            int idx = threadIdx.x + t * 256;
            int kg  = idx >> 5;
            int b   = idx & 31;
            float4 h4 = *(const float4*)&hidden[b * HID_ + k0 + kc + kg * 4];
            sh[kg * 4 + 0][b] = h4.x;
            sh[kg * 4 + 1][b] = h4.y;
            sh[kg * 4 + 2][b] = h4.z;
            sh[kg * 4 + 3][b] = h4.w;
        }
        __syncthreads();

        const float* wp = W + (size_t)(k0 + kc) * TH_ + j0;
        for (int k = 0; k < 128; k += 8) {
            float4 w[8];
#pragma unroll
            for (int u = 0; u < 8; u++)                  // 8 LDG.128 in flight
                w[u] = *(const float4*)(wp + (size_t)u * TH_);
            wp += 8 * (size_t)TH_;
#pragma unroll
            for (int u = 0; u < 8; u++) {
                ulonglong2 hA = *(const ulonglong2*)&sh[k + u][bg];
                ulonglong2 hB = *(const ulonglong2*)&sh[k + u][bg + 4];
                u64 wd0 = pack2(w[u].x, w[u].x);
                u64 wd1 = pack2(w[u].y, w[u].y);
                u64 wd2 = pack2(w[u].z, w[u].z);
                u64 wd3 = pack2(w[u].w, w[u].w);
                acc[0][0] = fma2(hA.x, wd0, acc[0][0]);
                acc[1][0] = fma2(hA.x, wd1, acc[1][0]);
                acc[2][0] = fma2(hA.x, wd2, acc[2][0]);
                acc[3][0] = fma2(hA.x, wd3, acc[3][0]);
                acc[0][1] = fma2(hA.y, wd0, acc[0][1]);
                acc[1][1] = fma2(hA.y, wd1, acc[1][1]);
                acc[2][1] = fma2(hA.y, wd2, acc[2][1]);
                acc[3][1] = fma2(hA.y, wd3, acc[3][1]);
                acc[0][2] = fma2(hB.x, wd0, acc[0][2]);
                acc[1][2] = fma2(hB.x, wd1, acc[1][2]);
                acc[2][2] = fma2(hB.x, wd2, acc[2][2]);
                acc[3][2] = fma2(hB.x, wd3, acc[3][2]);
                acc[0][3] = fma2(hB.y, wd0, acc[0][3]);
                acc[1][3] = fma2(hB.y, wd1, acc[1][3]);
                acc[2][3] = fma2(hB.y, wd2, acc[2][3]);
                acc[3][3] = fma2(hB.y, wd3, acc[3][3]);
            }
        }
    }

    float* outp = &g_part[blockIdx.y][0];
#pragma unroll
    for (int p = 0; p < 4; p++) {
        float4 flo = make_float4(lo2(acc[0][p]), lo2(acc[1][p]), lo2(acc[2][p]), lo2(acc[3][p]));
        float4 fhi = make_float4(hi2(acc[0][p]), hi2(acc[1][p]), hi2(acc[2][p]), hi2(acc[3][p]));
        *(float4*)&outp[(bg + 2 * p) * TH_ + j0]     = flo;
        *(float4*)&outp[(bg + 2 * p + 1) * TH_ + j0] = fhi;
    }
}

// Reduce KSPLIT partials -> g_qkv. grid 384, block 256, float4 per thread.
__global__ __launch_bounds__(256) void qkv_reduce_kernel(int dummy) {
    int i = (blockIdx.x * 256 + threadIdx.x) * 4;
    float4 r = *(const float4*)&g_part[0][i];
#pragma unroll
    for (int p = 1; p < KSPLIT; p++) {
        float4 a = *(const float4*)&g_part[p][i];
        r.x += a.x; r.y += a.y; r.z += a.z; r.w += a.w;
    }
    *(float4*)&g_qkv[i] = r;
}

// ---------------------------------------------------------------------------
// Kernel 2a: rope table (only DP math, 2048 threads)
// ---------------------------------------------------------------------------
__global__ __launch_bounds__(64) void rope_table(const int* __restrict__ hist) {
    const int b = blockIdx.x;
    const int i = threadIdx.x;
    double invd = exp(-(double)i / 64.0 * 9.210340371976184);  // ln(10000)
    double angd = fmod((double)hist[b] * invd, 6.283185307179586476925286766559);
    g_cs[b][i][0] = cosf((float)angd);
    g_cs[b][i][1] = sinf((float)angd);
}

// Kernel 2b: apply rope to q,k. grid (32, 64): y = part*32+h. block 128.
__global__ __launch_bounds__(128) void rope_apply(int dummy) {
    const int b    = blockIdx.x;
    const int part = blockIdx.y >> 5;
    const int h    = blockIdx.y & 31;
    const int d    = threadIdx.x;
    const float c = g_cs[b][d & 63][0];
    const float s = g_cs[b][d & 63][1];

    float* p = &g_qkv[b * TH_ + part * HID_ + h * D_];
    float x  = p[d];
    float xr = (d < 64) ? -p[d + 64] : p[d - 64];
    __syncthreads();
    p[d] = x * c + xr * s;
}

// ---------------------------------------------------------------------------
// Kernel 3: attention, two-phase. grid = B*H blocks, 256 threads.
// Phase 1 unroll 4 (K-stream MLP 4/warp); phase 2 unroll 8 (V stream).
// ---------------------------------------------------------------------------
__global__ __launch_bounds__(256) void attn_kernel(const float* __restrict__ kcache,
                                                   const float* __restrict__ vcache,
                                                   const int* __restrict__ hist,
                                                   const int* __restrict__ boff) {
    const int b = blockIdx.x >> 5;
    const int h = blockIdx.x & 31;
    const int tid  = threadIdx.x;
    const int lane = tid & 31;
    const int wid  = tid >> 5;

    __shared__ int   s_blk[NBLK_];
    __shared__ float s_sc[1024];
    __shared__ float s_red[8];
    __shared__ float s_half[128];

    if (tid < NBLK_) s_blk[tid] = boff[b * NBLK_ + tid];
    __syncthreads();

    const int pos = hist[b];
    const float scale = 0.08838834764831845f;  // 1/sqrt(128)
    const float4 q4 = *(const float4*)&g_qkv[b * TH_ + h * D_ + lane * 4];

    // ---- phase 1: scores ----
    float mloc = -1e30f;
    int s = wid;
    for (; s + 24 < pos; s += 32) {
        float4 k[4];
        int    sp[4];
#pragma unroll
        for (int u = 0; u < 4; u++) {
            sp[u] = s + u * 8;
            int a = ((s_blk[sp[u] >> 6] * BS_ + (sp[u] & 63)) * H_ + h) * D_;
            k[u] = *(const float4*)&kcache[a + lane * 4];
        }
        float dt[4];
#pragma unroll
        for (int u = 0; u < 4; u++)
            dt[u] = q4.x * k[u].x + q4.y * k[u].y + q4.z * k[u].z + q4.w * k[u].w;
#pragma unroll
        for (int o = 16; o > 0; o >>= 1)
#pragma unroll
            for (int u = 0; u < 4; u++)
                dt[u] += __shfl_xor_sync(0xffffffffu, dt[u], o);
#pragma unroll
        for (int u = 0; u < 4; u++) {
            dt[u] *= scale;
            mloc = fmaxf(mloc, dt[u]);
            if (lane == 0) s_sc[sp[u]] = dt[u];
        }
    }
    for (; s < pos; s += 8) {
        int a0 = ((s_blk[s >> 6] * BS_ + (s & 63)) * H_ + h) * D_;
        float4 k0 = *(const float4*)&kcache[a0 + lane * 4];
        float d0 = q4.x * k0.x + q4.y * k0.y + q4.z * k0.z + q4.w * k0.w;
#pragma unroll
        for (int o = 16; o > 0; o >>= 1) d0 += __shfl_xor_sync(0xffffffffu, d0, o);
        d0 *= scale;
        mloc = fmaxf(mloc, d0);
        if (lane == 0) s_sc[s] = d0;
    }
    if ((pos & 7) == wid) {      // fresh k at s == pos (ref writes cache first)
        const float* kp = &g_qkv[b * TH_ + HID_ + h * D_];
        float4 k0 = *(const float4*)&kp[lane * 4];
        float d0 = q4.x * k0.x + q4.y * k0.y + q4.z * k0.z + q4.w * k0.w;
#pragma unroll
        for (int o = 16; o > 0; o >>= 1) d0 += __shfl_xor_sync(0xffffffffu, d0, o);
        d0 *= scale;
        mloc = fmaxf(mloc, d0);
        if (lane == 0) s_sc[pos] = d0;
    }

    if (lane == 0) s_red[wid] = mloc;
    __syncthreads();
    float M = -1e30f;
#pragma unroll
    for (int w = 0; w < 8; w++) M = fmaxf(M, s_red[w]);

    float lsum = 0.f;
    for (int i = tid; i <= pos; i += 256) {
        float p = __expf(s_sc[i] - M);
        s_sc[i] = p;
        lsum += p;
    }
#pragma unroll
    for (int o = 16; o > 0; o >>= 1) lsum += __shfl_xor_sync(0xffffffffu, lsum, o);
    __syncthreads();
    if (lane == 0) s_red[wid] = lsum;
    __syncthreads();
    float L = 0.f;
#pragma unroll
    for (int w = 0; w < 8; w++) L += s_red[w];
    const float invL = 1.f / L;

    // ---- phase 2: out[d] = sum_s p[s] * v[s][d], coalesced over d ----
    const int d    = tid & 127;
    const int half = tid >> 7;
    float acc = 0.f;
#pragma unroll 8
    for (int s2 = half; s2 < pos; s2 += 2) {
        int base = ((s_blk[s2 >> 6] * BS_ + (s2 & 63)) * H_ + h) * D_;
        acc += s_sc[s2] * vcache[base + d];
    }
    if ((pos & 1) == half)
        acc += s_sc[pos] * g_qkv[b * TH_ + 2 * HID_ + h * D_ + d];

    if (half == 0) s_half[d] = acc;
    __syncthreads();
    if (half == 1)
        g_attn[b * HID_ + h * D_ + d] = (acc + s_half[d]) * invL;
}

// ---------------------------------------------------------------------------
// Kernel 4: out = attn @ Wo^T, f32x2. block 128, warp = 2 rows x 16 batches.
// grid 1024 = 512 row-tiles x 2 batch-halves.
// ---------------------------------------------------------------------------
__global__ __launch_bounds__(128) void oproj_kernel(const float* __restrict__ Wo,
                                                    float* __restrict__ out) {
    __shared__ float s_attn[16][256];
    const int lane = threadIdx.x & 31;
    const int wid  = threadIdx.x >> 5;
    const int tile = blockIdx.x >> 1;
    const int bh   = (blockIdx.x & 1) * 16;
    const int i0   = tile * 8 + wid * 2;

    u64 acc[2][16];
#pragma unroll
    for (int r = 0; r < 2; r++)
#pragma unroll
        for (int b = 0; b < 16; b++) acc[r][b] = 0ull;

    for (int jt = 0; jt < HID_; jt += 256) {
        __syncthreads();
#pragma unroll
        for (int t = 0; t < 8; t++) {
            int idx = threadIdx.x + t * 128;
            int b   = idx >> 6;
            int jj  = (idx & 63) << 2;
            *(float4*)&s_attn[b][jj] = *(const float4*)&g_attn[(bh + b) * HID_ + jt + jj];
        }
        __syncthreads();

        const float* w = Wo + (size_t)i0 * HID_ + jt;
#pragma unroll
        for (int part = 0; part < 2; part++) {
            int j0 = part * 128 + lane * 4;
            ulonglong2 w0 = *(const ulonglong2*)&w[j0];
            ulonglong2 w1 = *(const ulonglong2*)&w[HID_ + j0];
#pragma unroll
            for (int b = 0; b < 16; b++) {
                ulonglong2 a = *(const ulonglong2*)&s_attn[b][j0];
                acc[0][b] = fma2(a.x, w0.x, acc[0][b]);
                acc[0][b] = fma2(a.y, w0.y, acc[0][b]);
                acc[1][b] = fma2(a.x, w1.x, acc[1][b]);
                acc[1][b] = fma2(a.y, w1.y, acc[1][b]);
            }
        }
    }

#pragma unroll
    for (int r = 0; r < 2; r++) {
        float res = 0.f;
#pragma unroll
        for (int b = 0; b < 16; b++) {
            float v = hadd2(acc[r][b]);
#pragma unroll
            for (int o = 16; o > 0; o >>= 1) v += __shfl_xor_sync(0xffffffffu, v, o);
            if (lane == b) res = v;
        }
        if (lane < 16) out[(bh + lane) * HID_ + i0 + r] = res;
    }
}

// ---------------------------------------------------------------------------
extern "C" void kernel_launch(void* const* d_in, const int* in_sizes, int n_in,
                              void* d_out, int out_size) {
    const float* hidden = (const float*)d_in[0];
    const float* W      = (const float*)d_in[1];
    const float* Wo     = (const float*)d_in[2];
    const float* kcache = (const float*)d_in[3];
    const float* vcache = (const float*)d_in[4];
    const int*   hist   = (const int*)d_in[5];
    const int*   boff   = (const int*)d_in[6];
    float*       out    = (float*)d_out;

    qkv_part_kernel<<<dim3(TH_ / 256, KSPLIT), 256>>>(hidden, W);
    qkv_reduce_kernel<<<B_ * TH_ / 1024, 256>>>(0);
    rope_table<<<B_, 64>>>(hist);
    rope_apply<<<dim3(B_, 2 * H_), 128>>>(0);
    attn_kernel<<<B_ * H_, 256>>>(kcache, vcache, hist, boff);
    oproj_kernel<<<1024, 128>>>(Wo, out);
}